// round 10
// baseline (speedup 1.0000x reference)
#include <cuda_runtime.h>
#include <cuda_fp16.h>
#include <math.h>
#include <stdint.h>

// ---------------------------------------------------------------------------
// Problem constants
// ---------------------------------------------------------------------------
#define BATCH   512
#define IN_DIM  256
#define OUT_DIM 256
#define NB      11
#define FPI     12
#define KDIM    (IN_DIM*FPI)     // 3072

// Fused GEMM config
#define BM 128
#define BN 64
#define BK 64
#define SK 8
#define KPC (KDIM/SK)            // 384
#define NCH (KPC/BK)             // 6 chunks
#define IPC 32                   // input dims per CTA (KPC/FPI)

#define ACHUNK 16384             // 128 rows x 128B
#define BCHUNK 8192              // 64 rows x 128B
#define ASZ (NCH*ACHUNK)         // 96 KB
#define BSZ (NCH*BCHUNK)         // 48 KB
#define SMEM_TOTAL (ASZ + BSZ)   // 147456
#define EPI_STRIDE 68

// ---------------------------------------------------------------------------
// helpers
// ---------------------------------------------------------------------------
__device__ __forceinline__ uint32_t smem_u32(const void* p) {
    uint32_t a;
    asm("{ .reg .u64 t; cvta.to.shared.u64 t, %1; cvt.u32.u64 %0, t; }" : "=r"(a) : "l"(p));
    return a;
}
__device__ __forceinline__ void ldsm_x4(uint32_t& r0, uint32_t& r1, uint32_t& r2, uint32_t& r3, uint32_t a) {
    asm volatile("ldmatrix.sync.aligned.m8n8.x4.shared.b16 {%0,%1,%2,%3}, [%4];"
                 : "=r"(r0), "=r"(r1), "=r"(r2), "=r"(r3) : "r"(a));
}
__device__ __forceinline__ void mma16816(float* d, const uint32_t* a, uint32_t b0, uint32_t b1) {
    asm volatile(
        "mma.sync.aligned.m16n8k16.row.col.f32.f16.f16.f32 "
        "{%0,%1,%2,%3}, {%4,%5,%6,%7}, {%8,%9}, {%0,%1,%2,%3};"
        : "+f"(d[0]), "+f"(d[1]), "+f"(d[2]), "+f"(d[3])
        : "r"(a[0]), "r"(a[1]), "r"(a[2]), "r"(a[3]), "r"(b0), "r"(b1));
}
__device__ __forceinline__ uint32_t pack_h2(float a, float b) {
    __half2 h = __floats2half2_rn(a, b);
    return *reinterpret_cast<uint32_t*>(&h);
}

// ---------------------------------------------------------------------------
// Fused kernel: per-CTA feature+weight fill -> smem, then MMA, then RED out.
// grid = (4, 4, 8) = 128 CTAs (one wave), 256 threads (8 warps, 4m x 2n)
// ---------------------------------------------------------------------------
__global__ __launch_bounds__(256, 1) void kan_fused(const float* __restrict__ x,
                                                    const float* __restrict__ coef,
                                                    const float* __restrict__ rw,
                                                    const float* __restrict__ uw,
                                                    float* __restrict__ out)
{
    extern __shared__ __align__(1024) char smem[];
    const uint32_t sA = smem_u32(smem);
    const uint32_t sB = sA + ASZ;

    const int tid = threadIdx.x;
    const int wid = tid >> 5;
    const int lid = tid & 31;
    const int warp_m = wid & 3;
    const int warp_n = wid >> 2;

    const int n0 = blockIdx.x * BN;
    const int m0 = blockIdx.y * BM;
    const int i0 = blockIdx.z * IPC;

    // ---------------- fill A: features for b in [m0,m0+128), i in [i0,i0+32)
#pragma unroll
    for (int pp = 0; pp < (BM * IPC) / 256; ++pp) {
        const int p = tid + pp * 256;
        const int b = p >> 5;
        const int ii = p & 31;
        const float xv = x[(size_t)(m0 + b) * IN_DIM + i0 + ii];

        // closed-form local cubic B-spline on uniform grid [-1.75, 1.75]
        float xs = (xv + 1.75f) * 4.0f;
        float fc = floorf(xs);
        int   c  = (int)fc;
        float t  = xs - fc;
        float it = 1.0f - t;
        float t2 = t * t, t3 = t2 * t;
        float w0 = it * it * it * (1.0f / 6.0f);
        float w1 = (3.0f * t3 - 6.0f * t2 + 4.0f) * (1.0f / 6.0f);
        float w2 = (-3.0f * t3 + 3.0f * t2 + 3.0f * t + 1.0f) * (1.0f / 6.0f);
        float w3 = t3 * (1.0f / 6.0f);
        bool in_range = (c >= 0 && c <= 13);

        float f[12];
#pragma unroll
        for (int j = 0; j < 11; ++j) {
            int q = j - c + 3;
            float w = (q == 0) ? w0 : (q == 1) ? w1 : (q == 2) ? w2 : w3;
            f[j] = (in_range && q >= 0 && q <= 3) ? w : 0.0f;
        }
        f[11] = xv / (1.0f + __expf(-xv));

#pragma unroll
        for (int t6 = 0; t6 < 6; ++t6) {
            const int kl = ii * FPI + 2 * t6;
            const int ch = kl >> 6;
            const int byte = (kl & 63) * 2;
            const uint32_t addr = sA + ch * ACHUNK + b * 128 + (byte ^ ((b & 7) << 4));
            *(uint32_t*)(smem + (addr - sA) + 0) = pack_h2(f[2 * t6], f[2 * t6 + 1]);
        }
    }

    // ---------------- fill B: weights for o in [n0,n0+64), i in [i0,i0+32)
#pragma unroll
    for (int pp = 0; pp < (BN * IPC) / 256; ++pp) {
        const int p = tid + pp * 256;
        const int o = p >> 5;
        const int ii = p & 31;
        const int gi = (n0 + o) * IN_DIM + i0 + ii;
        const float u = uw[gi];
        const float* cf = &coef[(size_t)gi * NB];
        float w[12];
#pragma unroll
        for (int j = 0; j < NB; ++j) w[j] = u * cf[j];
        w[11] = rw[gi];

#pragma unroll
        for (int t6 = 0; t6 < 6; ++t6) {
            const int kl = ii * FPI + 2 * t6;
            const int ch = kl >> 6;
            const int byte = (kl & 63) * 2;
            const uint32_t addr = sB + ch * BCHUNK + o * 128 + (byte ^ ((o & 7) << 4));
            *(uint32_t*)(smem + (addr - sA)) = pack_h2(w[2 * t6], w[2 * t6 + 1]);
        }
    }

    __syncthreads();

    // ---------------- MMA mainloop: 6 chunks x 4 ks, no barriers
    float acc[2][4][4];
#pragma unroll
    for (int i = 0; i < 2; ++i)
#pragma unroll
        for (int j = 0; j < 4; ++j)
#pragma unroll
            for (int q = 0; q < 4; ++q) acc[i][j][q] = 0.0f;

#pragma unroll
    for (int c = 0; c < NCH; ++c) {
        const uint32_t stA = sA + c * ACHUNK;
        const uint32_t stB = sB + c * BCHUNK;
#pragma unroll
        for (int ks = 0; ks < 4; ++ks) {
            uint32_t af[2][4];
#pragma unroll
            for (int mt = 0; mt < 2; ++mt) {
                const int r = warp_m * 32 + mt * 16 + (lid & 15);
                const int cb = ks * 32 + ((lid >> 4) << 4);
                ldsm_x4(af[mt][0], af[mt][1], af[mt][2], af[mt][3],
                        stA + r * 128 + (cb ^ ((r & 7) << 4)));
            }
            uint32_t bf[8];
#pragma unroll
            for (int nt = 0; nt < 2; ++nt) {
                const int r = warp_n * 32 + nt * 16 + (lid & 7) + ((lid >> 4) << 3);
                const int cb = ks * 32 + (((lid >> 3) & 1) << 4);
                ldsm_x4(bf[nt * 4 + 0], bf[nt * 4 + 1], bf[nt * 4 + 2], bf[nt * 4 + 3],
                        stB + r * 128 + (cb ^ ((r & 7) << 4)));
            }
#pragma unroll
            for (int mt = 0; mt < 2; ++mt)
#pragma unroll
                for (int j = 0; j < 4; ++j)
                    mma16816(acc[mt][j], af[mt], bf[j * 2], bf[j * 2 + 1]);
        }
    }

    // ---------------- epilogue: stage fp32 tile in smem, then float4 REDs
    __syncthreads();
    float* stile = (float*)smem;   // [128][EPI_STRIDE] = 34816 B (inside A region)
    {
        const int r0 = warp_m * 32 + (lid >> 2);
        const int c0 = warp_n * 32 + (lid & 3) * 2;
#pragma unroll
        for (int mt = 0; mt < 2; ++mt) {
#pragma unroll
            for (int j = 0; j < 4; ++j) {
                const int rr = r0 + mt * 16;
                const int cc = c0 + j * 8;
                stile[rr * EPI_STRIDE + cc]           = acc[mt][j][0];
                stile[rr * EPI_STRIDE + cc + 1]       = acc[mt][j][1];
                stile[(rr + 8) * EPI_STRIDE + cc]     = acc[mt][j][2];
                stile[(rr + 8) * EPI_STRIDE + cc + 1] = acc[mt][j][3];
            }
        }
    }
    __syncthreads();
#pragma unroll
    for (int q = 0; q < 8; ++q) {
        const int li = tid + 256 * q;      // 0..2047 float4 slots
        const int r  = li >> 4;
        const int cq = (li & 15) << 2;
        const float4 v = *(const float4*)&stile[r * EPI_STRIDE + cq];
        atomicAdd((float4*)&out[(size_t)(m0 + r) * OUT_DIM + n0 + cq], v);
    }
}

// ---------------------------------------------------------------------------
// Launch
// ---------------------------------------------------------------------------
extern "C" void kernel_launch(void* const* d_in, const int* in_sizes, int n_in,
                              void* d_out, int out_size)
{
    const float* x    = (const float*)d_in[0];
    const float* coef = (const float*)d_in[1];
    const float* rw   = (const float*)d_in[2];
    const float* uw   = (const float*)d_in[3];
    float* out = (float*)d_out;

    cudaFuncSetAttribute(kan_fused, cudaFuncAttributeMaxDynamicSharedMemorySize, SMEM_TOTAL);
    cudaMemsetAsync(out, 0, (size_t)BATCH * OUT_DIM * sizeof(float));
    kan_fused<<<dim3(OUT_DIM / BN, BATCH / BM, SK), 256, SMEM_TOTAL>>>(x, coef, rw, uw, out);
}

// round 11
// speedup vs baseline: 1.9876x; 1.9876x over previous
#include <cuda_runtime.h>
#include <cuda_fp16.h>
#include <math.h>
#include <stdint.h>

// ---------------------------------------------------------------------------
// Problem constants
// ---------------------------------------------------------------------------
#define BATCH   512
#define IN_DIM  256
#define OUT_DIM 256
#define NB      11
#define FPI     12
#define KDIM    (IN_DIM*FPI)     // 3072

// GEMM config: one exact wave
#define BM 128
#define BN 64
#define BK 64
#define SK 8
#define KPC (KDIM/SK)            // 384
#define NCH (KPC/BK)             // 6 chunks, all resident in smem

#define ACHUNK 16384             // 128 rows x 128B
#define BCHUNK 8192              // 64 rows x 128B
#define ASZ (NCH*ACHUNK)         // 96 KB? no: 6*16384 = 98304 -> too big with B!
// NOTE: A chunk holds 64 k-halfs = 128B/row; 6 chunks A = 98304 + B 49152 = 147456.
// That exceeds 227KB? No, fine (147456 < 232448). Keep full residency.
#define BSZ (NCH*BCHUNK)
#define SMEM_TOTAL (ASZ + BSZ)   // 147456
#define EPI_STRIDE 68

#define NTHREADS 512

// Scratch (device globals)
__device__ __half g_A[(size_t)BATCH   * KDIM];  // 3.1 MB
__device__ __half g_B[(size_t)OUT_DIM * KDIM];  // 1.5 MB

// ---------------------------------------------------------------------------
// helpers
// ---------------------------------------------------------------------------
__device__ __forceinline__ uint32_t smem_u32(const void* p) {
    uint32_t a;
    asm("{ .reg .u64 t; cvta.to.shared.u64 t, %1; cvt.u32.u64 %0, t; }" : "=r"(a) : "l"(p));
    return a;
}
__device__ __forceinline__ void cp_async16(uint32_t dst, const void* src) {
    asm volatile("cp.async.cg.shared.global [%0], [%1], 16;" :: "r"(dst), "l"(src));
}
__device__ __forceinline__ void cp_commit() {
    asm volatile("cp.async.commit_group;");
}
template <int N>
__device__ __forceinline__ void cp_wait() {
    asm volatile("cp.async.wait_group %0;" :: "n"(N));
}
__device__ __forceinline__ void ldsm_x4(uint32_t& r0, uint32_t& r1, uint32_t& r2, uint32_t& r3, uint32_t a) {
    asm volatile("ldmatrix.sync.aligned.m8n8.x4.shared.b16 {%0,%1,%2,%3}, [%4];"
                 : "=r"(r0), "=r"(r1), "=r"(r2), "=r"(r3) : "r"(a));
}
__device__ __forceinline__ void mma16816(float* d, const uint32_t* a, uint32_t b0, uint32_t b1) {
    asm volatile(
        "mma.sync.aligned.m16n8k16.row.col.f32.f16.f16.f32 "
        "{%0,%1,%2,%3}, {%4,%5,%6,%7}, {%8,%9}, {%0,%1,%2,%3};"
        : "+f"(d[0]), "+f"(d[1]), "+f"(d[2]), "+f"(d[3])
        : "r"(a[0]), "r"(a[1]), "r"(a[2]), "r"(a[3]), "r"(b0), "r"(b1));
}

// ---------------------------------------------------------------------------
// Kernel 1 (merged prep): blocks [0,512) -> features (+ zero out), rest -> weights
// ---------------------------------------------------------------------------
__global__ __launch_bounds__(256) void prep_kernel(const float* __restrict__ x,
                                                   const float* __restrict__ coef,
                                                   const float* __restrict__ rw,
                                                   const float* __restrict__ uw,
                                                   float* __restrict__ out)
{
    if (blockIdx.x < 512) {
        int idx = blockIdx.x * blockDim.x + threadIdx.x;   // b*256 + i
        out[idx] = 0.0f;                                    // fused output zeroing
        float xv = x[idx];

        float xs = (xv + 1.75f) * 4.0f;
        float fc = floorf(xs);
        int   c  = (int)fc;
        float t  = xs - fc;
        float it = 1.0f - t;
        float t2 = t * t, t3 = t2 * t;
        float w0 = it * it * it * (1.0f / 6.0f);
        float w1 = (3.0f * t3 - 6.0f * t2 + 4.0f) * (1.0f / 6.0f);
        float w2 = (-3.0f * t3 + 3.0f * t2 + 3.0f * t + 1.0f) * (1.0f / 6.0f);
        float w3 = t3 * (1.0f / 6.0f);
        bool in_range = (c >= 0 && c <= 13);

        float f[12];
#pragma unroll
        for (int j = 0; j < 11; ++j) {
            int p = j - c + 3;
            float w = (p == 0) ? w0 : (p == 1) ? w1 : (p == 2) ? w2 : w3;
            f[j] = (in_range && p >= 0 && p <= 3) ? w : 0.0f;
        }
        f[11] = xv / (1.0f + __expf(-xv));

        union { __half h[12]; uint2 u[3]; } hv;
#pragma unroll
        for (int j = 0; j < 12; ++j) hv.h[j] = __float2half_rn(f[j]);

        int b = idx >> 8, i = idx & 255;
        uint2* s = (uint2*)&g_A[(size_t)b * KDIM + i * FPI];
#pragma unroll
        for (int j = 0; j < 3; ++j) s[j] = hv.u[j];
    } else {
        int idx = (blockIdx.x - 512) * blockDim.x + threadIdx.x;   // o*256 + i
        float u = uw[idx];
        const float* c = &coef[(size_t)idx * NB];
        float w[12];
#pragma unroll
        for (int j = 0; j < NB; ++j) w[j] = u * c[j];
        w[11] = rw[idx];

        union { __half h[12]; uint2 u2[3]; } hv;
#pragma unroll
        for (int j = 0; j < 12; ++j) hv.h[j] = __float2half_rn(w[j]);

        int o = idx >> 8, i = idx & 255;
        uint2* s = (uint2*)&g_B[(size_t)o * KDIM + i * FPI];
#pragma unroll
        for (int j = 0; j < 3; ++j) s[j] = hv.u2[j];
    }
}

// ---------------------------------------------------------------------------
// Kernel 2: fp16 mma.sync GEMM, one wave: grid (4,4,8)=128 CTAs, 512 threads.
// All 6 K-chunks bulk-loaded upfront (6 commit groups), progressive waits.
// 16 warps: warp_m = wid&3 (32 rows), warp_n = wid>>2 (16 cols).
// ---------------------------------------------------------------------------
__global__ __launch_bounds__(NTHREADS, 1) void gemm_mma(float* __restrict__ out)
{
    extern __shared__ __align__(1024) char smem[];
    const uint32_t sA = smem_u32(smem);
    const uint32_t sB = sA + ASZ;

    const int tid = threadIdx.x;
    const int wid = tid >> 5;
    const int lid = tid & 31;
    const int warp_m = wid & 3;       // 0..3 -> 32-row band
    const int warp_n = wid >> 2;      // 0..3 -> 16-col band

    const int n0 = blockIdx.x * BN;
    const int m0 = blockIdx.y * BM;
    const int k00 = blockIdx.z * KPC;

    const __half* A = g_A;
    const __half* B = g_B;

    // ---- bulk-issue all 6 chunks, one commit group each ----
#pragma unroll
    for (int c = 0; c < NCH; ++c) {
        const int kb = k00 + c * BK;
        const uint32_t stA = sA + c * ACHUNK;
        const uint32_t stB = sB + c * BCHUNK;
        // A: 1024 x 16B, 2 per thread
#pragma unroll
        for (int t = 0; t < 2; ++t) {
            const int li = tid + NTHREADS * t;
            const int r = li >> 3;
            const int cb = (li & 7) << 4;
            cp_async16(stA + r * 128 + (cb ^ ((r & 7) << 4)),
                       A + (size_t)(m0 + r) * KDIM + kb + (cb >> 1));
        }
        // B: 512 x 16B, 1 per thread
        {
            const int r = tid >> 3;
            const int cb = (tid & 7) << 4;
            cp_async16(stB + r * 128 + (cb ^ ((r & 7) << 4)),
                       B + (size_t)(n0 + r) * KDIM + kb + (cb >> 1));
        }
        cp_commit();
    }

    float acc[2][2][4];
#pragma unroll
    for (int i = 0; i < 2; ++i)
#pragma unroll
        for (int j = 0; j < 2; ++j)
#pragma unroll
            for (int q = 0; q < 4; ++q) acc[i][j][q] = 0.0f;

    // ---- mainloop: progressive waits, 4 ks per chunk ----
#pragma unroll
    for (int c = 0; c < NCH; ++c) {
        switch (c) {   // compile-time folded under full unroll
            case 0: cp_wait<5>(); break;
            case 1: cp_wait<4>(); break;
            case 2: cp_wait<3>(); break;
            case 3: cp_wait<2>(); break;
            case 4: cp_wait<1>(); break;
            default: cp_wait<0>(); break;
        }
        __syncthreads();
        const uint32_t stA = sA + c * ACHUNK;
        const uint32_t stB = sB + c * BCHUNK;

#pragma unroll
        for (int ks = 0; ks < 4; ++ks) {
            uint32_t af[2][4];
#pragma unroll
            for (int mt = 0; mt < 2; ++mt) {
                const int r = warp_m * 32 + mt * 16 + (lid & 15);
                const int cb = ks * 32 + ((lid >> 4) << 4);
                ldsm_x4(af[mt][0], af[mt][1], af[mt][2], af[mt][3],
                        stA + r * 128 + (cb ^ ((r & 7) << 4)));
            }
            // B: one x4 covers both n8 tiles x k16 of this warp's 16-col band
            uint32_t bf[4];
            {
                const int r = warp_n * 16 + (lid & 7) + ((lid >> 4) << 3);
                const int cb = ks * 32 + (((lid >> 3) & 1) << 4);
                ldsm_x4(bf[0], bf[1], bf[2], bf[3],
                        stB + r * 128 + (cb ^ ((r & 7) << 4)));
            }
#pragma unroll
            for (int mt = 0; mt < 2; ++mt) {
                mma16816(acc[mt][0], af[mt], bf[0], bf[1]);
                mma16816(acc[mt][1], af[mt], bf[2], bf[3]);
            }
        }
    }

    // ---- epilogue: stage fp32 tile in smem, then float4 vector REDs ----
    __syncthreads();
    float* stile = (float*)smem;   // [128][EPI_STRIDE] = 34816 B
    {
        const int r0 = warp_m * 32 + (lid >> 2);
        const int c0 = warp_n * 16 + (lid & 3) * 2;
#pragma unroll
        for (int mt = 0; mt < 2; ++mt) {
#pragma unroll
            for (int j = 0; j < 2; ++j) {
                const int rr = r0 + mt * 16;
                const int cc = c0 + j * 8;
                stile[rr * EPI_STRIDE + cc]           = acc[mt][j][0];
                stile[rr * EPI_STRIDE + cc + 1]       = acc[mt][j][1];
                stile[(rr + 8) * EPI_STRIDE + cc]     = acc[mt][j][2];
                stile[(rr + 8) * EPI_STRIDE + cc + 1] = acc[mt][j][3];
            }
        }
    }
    __syncthreads();
#pragma unroll
    for (int q = 0; q < 4; ++q) {
        const int li = tid + NTHREADS * q;   // 0..2047 float4 slots
        const int r  = li >> 4;
        const int cq = (li & 15) << 2;
        const float4 v = *(const float4*)&stile[r * EPI_STRIDE + cq];
        atomicAdd((float4*)&out[(size_t)(m0 + r) * OUT_DIM + n0 + cq], v);
    }
}

// ---------------------------------------------------------------------------
// Launch
// ---------------------------------------------------------------------------
extern "C" void kernel_launch(void* const* d_in, const int* in_sizes, int n_in,
                              void* d_out, int out_size)
{
    const float* x    = (const float*)d_in[0];
    const float* coef = (const float*)d_in[1];
    const float* rw   = (const float*)d_in[2];
    const float* uw   = (const float*)d_in[3];
    float* out = (float*)d_out;

    cudaFuncSetAttribute(gemm_mma, cudaFuncAttributeMaxDynamicSharedMemorySize, SMEM_TOTAL);
    prep_kernel<<<768, 256>>>(x, coef, rw, uw, out);
    gemm_mma<<<dim3(OUT_DIM / BN, BATCH / BM, SK), NTHREADS, SMEM_TOTAL>>>(out);
}